// round 1
// baseline (speedup 1.0000x reference)
#include <cuda_runtime.h>
#include <cstdint>

// Problem constants
#define N_ROWS 2048
#define MUL    128
#define G_SEG  32
#define W_FLAT (128*128*3)   // per-group weight floats
#define TILE_R 16            // rows per tile (each tile within one segment)
#define MAX_TILES 160        // sum ceil(c_g/16) <= 128 + 32 = 160

// Tile work list built on device each launch (deterministic, alloc-free)
__device__ int g_tile_start[MAX_TILES];
__device__ int g_tile_cnt[MAX_TILES];
__device__ int g_tile_seg[MAX_TILES];
__device__ int g_ntiles;

// ---------------------------------------------------------------------------
// Setup: one warp computes segment offsets from `repeats` and emits the
// segment-aware tile list.
// ---------------------------------------------------------------------------
__global__ void build_tiles_kernel(const int* __restrict__ repeats) {
    int t = threadIdx.x;          // 0..31
    int cnt = repeats[t];

    // inclusive scan of counts
    int inc = cnt;
    #pragma unroll
    for (int off = 1; off < 32; off <<= 1) {
        int v = __shfl_up_sync(0xFFFFFFFFu, inc, off);
        if (t >= off) inc += v;
    }
    int start = inc - cnt;        // exclusive prefix = segment start row

    // tiles for this segment
    int ntile = (cnt + TILE_R - 1) / TILE_R;
    int tinc = ntile;
    #pragma unroll
    for (int off = 1; off < 32; off <<= 1) {
        int v = __shfl_up_sync(0xFFFFFFFFu, tinc, off);
        if (t >= off) tinc += v;
    }
    int tstart = tinc - ntile;

    for (int k = 0; k < ntile; k++) {
        int idx = tstart + k;
        g_tile_start[idx] = start + k * TILE_R;
        int rem = cnt - k * TILE_R;
        g_tile_cnt[idx]   = rem < TILE_R ? rem : TILE_R;
        g_tile_seg[idx]   = t;
    }
    if (t == 31) g_ntiles = tinc;
}

// ---------------------------------------------------------------------------
// Main GEMM kernel, templated on irrep dim D.
// Block: 256 threads = 16 rows x 16 output-octets.
//   thread t: r = t>>4 (row in tile), o0 = (t&15)*8 (8 consecutive outputs)
// Computes y[n, o, i] = alpha * sum_m x[n, m, i] * w[g, m, o]
//   x layout: (N, 128, D) row-major ; w slice: wg[m*128 + o] ; y: (N, 128, D)
// ---------------------------------------------------------------------------
template <int D>
__global__ __launch_bounds__(256)
void irreps_linear_kernel(const float* __restrict__ x,
                          const float* __restrict__ w,
                          float* __restrict__ out,
                          int woff) {
    int tile = blockIdx.x;
    if (tile >= g_ntiles) return;

    const int n0  = g_tile_start[tile];
    const int cnt = g_tile_cnt[tile];
    const int g   = g_tile_seg[tile];

    const float* __restrict__ wg = w + (size_t)g * W_FLAT + woff;  // [m][o]

    __shared__ float Ws[32 * 128];          // K-chunk of W: [m][o], 16 KB
    __shared__ float Xs[TILE_R][32 * D];    // [row][m*D + i]

    const int t  = threadIdx.x;
    const int r  = t >> 4;
    const int o0 = (t & 15) * 8;

    float acc[D][8];
    #pragma unroll
    for (int i = 0; i < D; i++)
        #pragma unroll
        for (int j = 0; j < 8; j++) acc[i][j] = 0.0f;

    for (int mc = 0; mc < 128; mc += 32) {
        __syncthreads();

        // --- stage W chunk: 32x128 floats = 1024 float4, 4 per thread ---
        {
            const float4* wg4 = reinterpret_cast<const float4*>(wg + mc * 128);
            float4* Ws4 = reinterpret_cast<float4*>(Ws);
            #pragma unroll
            for (int k = 0; k < 4; k++)
                Ws4[t + k * 256] = wg4[t + k * 256];
        }

        // --- stage X chunk: 16 rows x 32*D contiguous floats each ---
        {
            const int chunk = 32 * D;
            #pragma unroll
            for (int idx = t; idx < TILE_R * chunk; idx += 256) {
                int rr = idx / chunk;
                int c  = idx - rr * chunk;
                float v = 0.0f;
                if (rr < cnt)
                    v = x[(size_t)(n0 + rr) * (128 * D) + mc * D + c];
                Xs[rr][c] = v;
            }
        }
        __syncthreads();

        #pragma unroll
        for (int m = 0; m < 32; m++) {
            const float4* wrow = reinterpret_cast<const float4*>(Ws + m * 128 + o0);
            float4 wa = wrow[0];
            float4 wb = wrow[1];
            float wv[8] = {wa.x, wa.y, wa.z, wa.w, wb.x, wb.y, wb.z, wb.w};

            float xv[D];
            #pragma unroll
            for (int i = 0; i < D; i++) xv[i] = Xs[r][m * D + i];

            #pragma unroll
            for (int i = 0; i < D; i++)
                #pragma unroll
                for (int j = 0; j < 8; j++)
                    acc[i][j] = fmaf(xv[i], wv[j], acc[i][j]);
        }
    }

    // --- store: y[n, o, i], alpha = 1/sqrt(G*MUL) = 1/64 exactly ---
    if (r < cnt) {
        const float alpha = 0.015625f;
        size_t base = (size_t)(n0 + r) * (128 * D);
        #pragma unroll
        for (int j = 0; j < 8; j++) {
            size_t ob = base + (size_t)(o0 + j) * D;
            #pragma unroll
            for (int i = 0; i < D; i++)
                out[ob + i] = acc[i][j] * alpha;
        }
    }
}

// ---------------------------------------------------------------------------
// Launch: inputs in metadata order: x0, x1, x2, w, repeats. Output is the
// concatenation y0 | y1 | y2 (float32).
// ---------------------------------------------------------------------------
extern "C" void kernel_launch(void* const* d_in, const int* in_sizes, int n_in,
                              void* d_out, int out_size) {
    const float* x0 = (const float*)d_in[0];   // (2048,128,1)
    const float* x1 = (const float*)d_in[1];   // (2048,128,3)
    const float* x2 = (const float*)d_in[2];   // (2048,128,5)
    const float* w  = (const float*)d_in[3];   // (32, 49152)
    const int*   rp = (const int*)d_in[4];     // (32,)
    float* out = (float*)d_out;

    build_tiles_kernel<<<1, 32>>>(rp);

    const size_t y0_elems = (size_t)N_ROWS * 128 * 1;
    const size_t y1_elems = (size_t)N_ROWS * 128 * 3;

    irreps_linear_kernel<1><<<MAX_TILES, 256>>>(x0, w, out, 0);
    irreps_linear_kernel<3><<<MAX_TILES, 256>>>(x1, w, out + y0_elems, 128 * 128);
    irreps_linear_kernel<5><<<MAX_TILES, 256>>>(x2, w, out + y0_elems + y1_elems, 2 * 128 * 128);
}

// round 2
// speedup vs baseline: 1.1290x; 1.1290x over previous
#include <cuda_runtime.h>
#include <cstdint>

#define N_ROWS 2048
#define W_FLAT (128*128*3)   // per-group weight floats
#define TILE_R 16
#define MAX_TILES 160

// Tile work list (device-built each launch; deterministic, alloc-free)
__device__ int g_tile_start[MAX_TILES];
__device__ int g_tile_cnt[MAX_TILES];
__device__ int g_tile_seg[MAX_TILES];
__device__ int g_ntiles;

// ---------------------------------------------------------------------------
// Setup: one warp scans `repeats` and emits segment-aware 16-row tiles.
// ---------------------------------------------------------------------------
__global__ void build_tiles_kernel(const int* __restrict__ repeats) {
    int t = threadIdx.x;          // 0..31
    int cnt = repeats[t];

    int inc = cnt;
    #pragma unroll
    for (int off = 1; off < 32; off <<= 1) {
        int v = __shfl_up_sync(0xFFFFFFFFu, inc, off);
        if (t >= off) inc += v;
    }
    int start = inc - cnt;

    int ntile = (cnt + TILE_R - 1) / TILE_R;
    int tinc = ntile;
    #pragma unroll
    for (int off = 1; off < 32; off <<= 1) {
        int v = __shfl_up_sync(0xFFFFFFFFu, tinc, off);
        if (t >= off) tinc += v;
    }
    int tstart = tinc - ntile;

    for (int k = 0; k < ntile; k++) {
        int idx = tstart + k;
        g_tile_start[idx] = start + k * TILE_R;
        int rem = cnt - k * TILE_R;
        g_tile_cnt[idx]   = rem < TILE_R ? rem : TILE_R;
        g_tile_seg[idx]   = t;
    }
    if (t == 31) g_ntiles = tinc;
}

// ---------------------------------------------------------------------------
// Packed f32x2 helpers (Blackwell FFMA2 — only reachable via PTX)
// ---------------------------------------------------------------------------
__device__ __forceinline__ uint64_t pack2(float lo, float hi) {
    uint64_t d;
    asm("mov.b64 %0, {%1,%2};" : "=l"(d) : "f"(lo), "f"(hi));
    return d;
}
__device__ __forceinline__ void unpack2(uint64_t v, float& lo, float& hi) {
    asm("mov.b64 {%0,%1}, %2;" : "=f"(lo), "=f"(hi) : "l"(v));
}
__device__ __forceinline__ uint64_t ffma2(uint64_t a, uint64_t b, uint64_t c) {
    uint64_t d;
    asm("fma.rn.f32x2 %0, %1, %2, %3;" : "=l"(d) : "l"(a), "l"(b), "l"(c));
    return d;
}

// ---------------------------------------------------------------------------
// Per-irrep GEMM body. Block: 256 thr = 16 rows x 16 output-octets.
// y[n,o,i] = alpha * sum_m x[n,m,i] * w[g,m,o]
// Double-buffered smem, one __syncthreads per K-chunk, FFMA2 inner loop.
// ---------------------------------------------------------------------------
template <int D>
__device__ __forceinline__ void body(const float* __restrict__ x,
                                     const float* __restrict__ w,
                                     float* __restrict__ out,
                                     int woff, float* smem) {
    int tile = blockIdx.x;
    if (tile >= g_ntiles) return;

    const int n0  = g_tile_start[tile];
    const int cnt = g_tile_cnt[tile];
    const int g   = g_tile_seg[tile];

    const float* __restrict__ wg = w + (size_t)g * W_FLAT + woff;  // [m][o]

    float* Ws = smem;                 // [2][32*128]
    float* Xs = smem + 2 * 32 * 128;  // [2][TILE_R*32*D]
    const int XS = TILE_R * 32 * D;

    const int t  = threadIdx.x;
    const int r  = t >> 4;
    const int o0 = (t & 15) * 8;

    uint64_t acc[D][4];
    #pragma unroll
    for (int i = 0; i < D; i++)
        #pragma unroll
        for (int j = 0; j < 4; j++) acc[i][j] = 0ull;

    // prefetch registers
    constexpr int NX = (TILE_R * 32 * D) / 256;  // exact for D=1,3,5
    float4 wreg[4];
    float  xreg[NX];

    auto gload = [&](int mc) {
        const float4* wg4 = reinterpret_cast<const float4*>(wg + mc * 128);
        #pragma unroll
        for (int k = 0; k < 4; k++) wreg[k] = wg4[t + k * 256];
        const int chunk = 32 * D;
        #pragma unroll
        for (int k = 0; k < NX; k++) {
            int idx = t + k * 256;
            int rr  = idx / chunk;
            int c   = idx - rr * chunk;
            float v = 0.0f;
            if (rr < cnt)
                v = x[(size_t)(n0 + rr) * (128 * D) + mc * D + c];
            xreg[k] = v;
        }
    };
    auto sstore = [&](int b) {
        float4* Ws4 = reinterpret_cast<float4*>(Ws + b * (32 * 128));
        #pragma unroll
        for (int k = 0; k < 4; k++) Ws4[t + k * 256] = wreg[k];
        float* Xb = Xs + b * XS;
        #pragma unroll
        for (int k = 0; k < NX; k++) Xb[t + k * 256] = xreg[k];
    };

    gload(0);
    sstore(0);
    __syncthreads();

    #pragma unroll
    for (int c = 0; c < 4; c++) {
        const int cur = c & 1;
        if (c < 3) gload((c + 1) * 32);

        const float* Wb = Ws + cur * (32 * 128);
        const float* Xb = Xs + cur * XS + r * (32 * D);

        #pragma unroll
        for (int m = 0; m < 32; m++) {
            // two LDS.128: four pre-paired 64-bit w operands (o0..o0+7)
            ulonglong2 wpa = *reinterpret_cast<const ulonglong2*>(Wb + m * 128 + o0);
            ulonglong2 wpb = *reinterpret_cast<const ulonglong2*>(Wb + m * 128 + o0 + 4);
            uint64_t wp[4] = {wpa.x, wpa.y, wpb.x, wpb.y};

            #pragma unroll
            for (int i = 0; i < D; i++) {
                float xv = Xb[m * D + i];
                uint64_t xd = pack2(xv, xv);
                #pragma unroll
                for (int j = 0; j < 4; j++)
                    acc[i][j] = ffma2(xd, wp[j], acc[i][j]);
            }
        }

        if (c < 3) {
            sstore(cur ^ 1);
            __syncthreads();
        }
    }

    if (r < cnt) {
        const float alpha = 0.015625f;   // 1/sqrt(32*128)
        float* ob = out + (size_t)(n0 + r) * (128 * D) + (size_t)o0 * D;
        #pragma unroll
        for (int j = 0; j < 4; j++) {
            #pragma unroll
            for (int i = 0; i < D; i++) {
                float lo, hi;
                unpack2(acc[i][j], lo, hi);
                ob[(2 * j + 0) * D + i] = lo * alpha;
                ob[(2 * j + 1) * D + i] = hi * alpha;
            }
        }
    }
}

// ---------------------------------------------------------------------------
// Fused kernel: blockIdx.y selects the irrep (heavy D=5 first).
// ---------------------------------------------------------------------------
__global__ __launch_bounds__(256, 2)
void irreps_fused_kernel(const float* __restrict__ x0,
                         const float* __restrict__ x1,
                         const float* __restrict__ x2,
                         const float* __restrict__ w,
                         float* __restrict__ out) {
    extern __shared__ float smem[];
    const size_t y0 = (size_t)N_ROWS * 128 * 1;
    const size_t y1 = (size_t)N_ROWS * 128 * 3;
    if (blockIdx.y == 0)
        body<5>(x2, w, out + y0 + y1, 2 * 128 * 128, smem);
    else if (blockIdx.y == 1)
        body<3>(x1, w, out + y0, 128 * 128, smem);
    else
        body<1>(x0, w, out, 0, smem);
}

// ---------------------------------------------------------------------------
extern "C" void kernel_launch(void* const* d_in, const int* in_sizes, int n_in,
                              void* d_out, int out_size) {
    const float* x0 = (const float*)d_in[0];   // (2048,128,1)
    const float* x1 = (const float*)d_in[1];   // (2048,128,3)
    const float* x2 = (const float*)d_in[2];   // (2048,128,5)
    const float* w  = (const float*)d_in[3];   // (32, 49152)
    const int*   rp = (const int*)d_in[4];     // (32,)
    float* out = (float*)d_out;

    // dyn smem: 2*32*128 (W) + 2*16*160 (X, D=5 worst case) floats = 52 KB
    const int smem_bytes = (2 * 32 * 128 + 2 * TILE_R * 32 * 5) * 4;
    cudaFuncSetAttribute(irreps_fused_kernel,
                         cudaFuncAttributeMaxDynamicSharedMemorySize, smem_bytes);

    build_tiles_kernel<<<1, 32>>>(rp);

    dim3 grid(MAX_TILES, 3);
    irreps_fused_kernel<<<grid, 256, smem_bytes>>>(x0, x1, x2, w, out);
}

// round 5
// speedup vs baseline: 1.5067x; 1.3345x over previous
#include <cuda_runtime.h>
#include <cstdint>

#define N_ROWS 2048
#define W_FLAT (128*128*3)
#define TILE_R 16
#define MAX_TILES 160

__device__ int g_tile_start[MAX_TILES];
__device__ int g_tile_cnt[MAX_TILES];
__device__ int g_tile_seg[MAX_TILES];
__device__ int g_ntiles;

// ---------------------------------------------------------------------------
__global__ void build_tiles_kernel(const int* __restrict__ repeats) {
    int t = threadIdx.x;
    int cnt = repeats[t];
    int inc = cnt;
    #pragma unroll
    for (int off = 1; off < 32; off <<= 1) {
        int v = __shfl_up_sync(0xFFFFFFFFu, inc, off);
        if (t >= off) inc += v;
    }
    int start = inc - cnt;
    int ntile = (cnt + TILE_R - 1) / TILE_R;
    int tinc = ntile;
    #pragma unroll
    for (int off = 1; off < 32; off <<= 1) {
        int v = __shfl_up_sync(0xFFFFFFFFu, tinc, off);
        if (t >= off) tinc += v;
    }
    int tstart = tinc - ntile;
    for (int k = 0; k < ntile; k++) {
        int idx = tstart + k;
        g_tile_start[idx] = start + k * TILE_R;
        int rem = cnt - k * TILE_R;
        g_tile_cnt[idx]   = rem < TILE_R ? rem : TILE_R;
        g_tile_seg[idx]   = t;
    }
    if (t == 31) g_ntiles = tinc;
}

// ---------------------------------------------------------------------------
__device__ __forceinline__ void unpack2(uint64_t v, float& lo, float& hi) {
    asm("mov.b64 {%0,%1}, %2;" : "=f"(lo), "=f"(hi) : "l"(v));
}
__device__ __forceinline__ uint64_t ffma2(uint64_t a, uint64_t b, uint64_t c) {
    uint64_t d;
    asm("fma.rn.f32x2 %0, %1, %2, %3;" : "=l"(d) : "l"(a), "l"(b), "l"(c));
    return d;
}

// ---------------------------------------------------------------------------
// Block: 256 thr. rg = t>>5 (warp-uniform row group: rows rg, rg+8),
// q = t&31 (outputs o0 = 4q .. 4q+3).
// X staged in smem as duplicated float2 (v,v) -> LDS.64 feeds FFMA2 directly.
// ---------------------------------------------------------------------------
template <int D>
__device__ __forceinline__ void body(const float* __restrict__ x,
                                     const float* __restrict__ w,
                                     float* __restrict__ out,
                                     int woff, float* smem) {
    int tile = blockIdx.x;
    if (tile >= g_ntiles) return;

    const int n0  = g_tile_start[tile];
    const int cnt = g_tile_cnt[tile];
    const int g   = g_tile_seg[tile];

    const float* __restrict__ wg = w + (size_t)g * W_FLAT + woff;

    float*  Ws = smem;                               // [2][32*128]
    float2* Xs = reinterpret_cast<float2*>(smem + 2 * 32 * 128);  // [2][16*32*D]
    const int XS2 = TILE_R * 32 * D;

    const int t  = threadIdx.x;
    const int rg = t >> 5;         // 0..7  (warp-uniform)
    const int q  = t & 31;         // 0..31
    const int o0 = q * 4;

    uint64_t acc[2][D][2];
    #pragma unroll
    for (int h = 0; h < 2; h++)
        #pragma unroll
        for (int i = 0; i < D; i++) {
            acc[h][i][0] = 0ull; acc[h][i][1] = 0ull;
        }

    constexpr int NX = 2 * D;      // X elems per thread per chunk (16*32*D/256)
    float4 wreg[4];
    float  xreg[NX];

    auto gload = [&](int mc) {
        const float4* wg4 = reinterpret_cast<const float4*>(wg + mc * 128);
        #pragma unroll
        for (int k = 0; k < 4; k++) wreg[k] = wg4[t + k * 256];
        const int chunk = 32 * D;
        #pragma unroll
        for (int k = 0; k < NX; k++) {
            int idx = t + k * 256;
            int rr  = idx / chunk;
            int c   = idx - rr * chunk;
            float v = 0.0f;
            if (rr < cnt)
                v = x[(size_t)(n0 + rr) * (128 * D) + mc * D + c];
            xreg[k] = v;
        }
    };
    auto sstore = [&](int b) {
        float4* Ws4 = reinterpret_cast<float4*>(Ws + b * (32 * 128));
        #pragma unroll
        for (int k = 0; k < 4; k++) Ws4[t + k * 256] = wreg[k];
        float2* Xb = Xs + b * XS2;
        #pragma unroll
        for (int k = 0; k < NX; k++)
            Xb[t + k * 256] = make_float2(xreg[k], xreg[k]);
    };

    gload(0);
    sstore(0);
    __syncthreads();

    for (int c = 0; c < 4; c++) {
        const int cur = c & 1;
        if (c < 3) gload((c + 1) * 32);

        const float* Wb = Ws + cur * (32 * 128);
        const uint64_t* X0 = reinterpret_cast<const uint64_t*>(
            Xs + cur * XS2 + rg * (32 * D));
        const uint64_t* X1 = reinterpret_cast<const uint64_t*>(
            Xs + cur * XS2 + (rg + 8) * (32 * D));

        #pragma unroll
        for (int m = 0; m < 32; m++) {
            ulonglong2 wp = *reinterpret_cast<const ulonglong2*>(Wb + m * 128 + o0);
            #pragma unroll
            for (int i = 0; i < D; i++) {
                uint64_t x0 = X0[m * D + i];
                uint64_t x1 = X1[m * D + i];
                acc[0][i][0] = ffma2(x0, wp.x, acc[0][i][0]);
                acc[0][i][1] = ffma2(x0, wp.y, acc[0][i][1]);
                acc[1][i][0] = ffma2(x1, wp.x, acc[1][i][0]);
                acc[1][i][1] = ffma2(x1, wp.y, acc[1][i][1]);
            }
        }

        if (c < 3) {
            sstore(cur ^ 1);
            __syncthreads();
        }
    }

    const float alpha = 0.015625f;   // 1/sqrt(32*128)
    #pragma unroll
    for (int h = 0; h < 2; h++) {
        int row = rg + 8 * h;
        if (row < cnt) {
            float* ob = out + (size_t)(n0 + row) * (128 * D) + (size_t)o0 * D;
            #pragma unroll
            for (int j = 0; j < 2; j++) {
                #pragma unroll
                for (int i = 0; i < D; i++) {
                    float lo, hi;
                    unpack2(acc[h][i][j], lo, hi);
                    ob[(2 * j + 0) * D + i] = lo * alpha;
                    ob[(2 * j + 1) * D + i] = hi * alpha;
                }
            }
        }
    }
}

// ---------------------------------------------------------------------------
__global__ __launch_bounds__(256, 2)
void irreps_fused_kernel(const float* __restrict__ x0,
                         const float* __restrict__ x1,
                         const float* __restrict__ x2,
                         const float* __restrict__ w,
                         float* __restrict__ out) {
    extern __shared__ float smem[];
    const size_t y0 = (size_t)N_ROWS * 128 * 1;
    const size_t y1 = (size_t)N_ROWS * 128 * 3;
    if (blockIdx.y == 0)
        body<5>(x2, w, out + y0 + y1, 2 * 128 * 128, smem);
    else if (blockIdx.y == 1)
        body<3>(x1, w, out + y0, 128 * 128, smem);
    else
        body<1>(x0, w, out, 0, smem);
}

// ---------------------------------------------------------------------------
extern "C" void kernel_launch(void* const* d_in, const int* in_sizes, int n_in,
                              void* d_out, int out_size) {
    const float* x0 = (const float*)d_in[0];
    const float* x1 = (const float*)d_in[1];
    const float* x2 = (const float*)d_in[2];
    const float* w  = (const float*)d_in[3];
    const int*   rp = (const int*)d_in[4];
    float* out = (float*)d_out;

    // smem: W 2*32*128 floats (32KB) + X 2*16*32*5 float2 (40KB) = 72KB
    const int smem_bytes = (2 * 32 * 128) * 4 + (2 * TILE_R * 32 * 5) * 8;
    cudaFuncSetAttribute(irreps_fused_kernel,
                         cudaFuncAttributeMaxDynamicSharedMemorySize, smem_bytes);

    build_tiles_kernel<<<1, 32>>>(rp);

    dim3 grid(MAX_TILES, 3);
    irreps_fused_kernel<<<grid, 256, smem_bytes>>>(x0, x1, x2, w, out);
}